// round 1
// baseline (speedup 1.0000x reference)
#include <cuda_runtime.h>

#define FIN 128
#define H1  64
#define H2  32
#define MAXN 100000
#define MAXE 1600000

// ---------------- device scratch (no allocations allowed) ----------------
__device__ float g_deg[MAXN];
__device__ float g_dinv[MAXN];
__device__ float g_invdeg[MAXN];
__device__ float g_xw1[MAXN * H1];
__device__ float g_agg1[MAXN * H1];
__device__ float g_xw2[MAXN * H2];
__device__ float g_agg2[MAXN * H2];
__device__ float g_sum1[H1], g_sq1[H1], g_scale1[H1], g_shift1[H1];
__device__ float g_sum2[H2], g_sq2[H2], g_scale2[H2], g_shift2[H2];
__device__ int   g_idx64;

// ---------------- helpers ----------------
__device__ __forceinline__ int load_src(const void* ei, int e, int i) {
    return g_idx64 ? (int)((const long long*)ei)[i] : ((const int*)ei)[i];
}
__device__ __forceinline__ int load_dst(const void* ei, int e, int i) {
    return g_idx64 ? (int)((const long long*)ei)[e + i] : ((const int*)ei)[e + i];
}

// ---------------- kernels ----------------

// Detect whether edge_index is int64 or int32 (deterministic, data-driven).
__global__ void k_detect(const void* ei, int n, int e) {
    if (threadIdx.x == 0 && blockIdx.x == 0) {
        const long long* p = (const long long*)ei;
        int m = e < 512 ? e : 512;
        int ok = 1;
        for (int i = 0; i < m; i++) {
            unsigned long long v = (unsigned long long)p[i];
            if (v >= (unsigned long long)n) { ok = 0; break; }
        }
        g_idx64 = ok;
    }
}

__global__ void k_zero(int n) {
    int i = blockIdx.x * blockDim.x + threadIdx.x;
    if (i < n) g_deg[i] = 0.f;
    if (i < H1) { g_sum1[i] = 0.f; g_sq1[i] = 0.f; }
    if (i < H2) { g_sum2[i] = 0.f; g_sq2[i] = 0.f; }
}

__global__ void k_deg(const void* ei, const float* __restrict__ ew, int e) {
    int i = blockIdx.x * blockDim.x + threadIdx.x;
    if (i >= e) return;
    int d = load_dst(ei, e, i);
    atomicAdd(&g_deg[d], ew[i]);
}

__global__ void k_degfin(int n) {
    int i = blockIdx.x * blockDim.x + threadIdx.x;
    if (i >= n) return;
    float d = g_deg[i] + 1.0f;
    g_dinv[i]   = rsqrtf(d);
    g_invdeg[i] = 1.0f / d;
}

// xw1 = x @ W1 ; agg1 = xw1 * invdeg (self-loop term).  Row-per-thread.
__global__ __launch_bounds__(256) void k_gemm1(const float* __restrict__ x,
                                               const float* __restrict__ W1, int n) {
    __shared__ float ws[FIN * H1];  // 32 KB
    int tid = threadIdx.x;
    for (int i = tid; i < FIN * H1 / 4; i += blockDim.x)
        ((float4*)ws)[i] = ((const float4*)W1)[i];
    __syncthreads();

    int row = blockIdx.x * blockDim.x + tid;
    if (row >= n) return;

    float acc[H1];
#pragma unroll
    for (int c = 0; c < H1; c++) acc[c] = 0.f;

    const float4* xr = (const float4*)(x + (long)row * FIN);
#pragma unroll 1
    for (int kb = 0; kb < FIN / 4; kb++) {
        float4 xv = xr[kb];
        const float* w0 = ws + (kb * 4) * H1;
#pragma unroll
        for (int c = 0; c < H1; c++) {
            acc[c] += xv.x * w0[c] + xv.y * w0[H1 + c]
                    + xv.z * w0[2 * H1 + c] + xv.w * w0[3 * H1 + c];
        }
    }
    float inv = g_invdeg[row];
    long base = (long)row * H1;
#pragma unroll
    for (int c = 0; c < H1; c++) {
        g_xw1[base + c]  = acc[c];
        g_agg1[base + c] = acc[c] * inv;
    }
}

// agg1[dst] += xw1[src] * (dinv[src]*ew*dinv[dst]);  warp per edge, 64 features.
__global__ void k_scatter1(const void* ei, const float* __restrict__ ew, int e) {
    int gt   = blockIdx.x * blockDim.x + threadIdx.x;
    int w    = gt >> 5;
    int lane = gt & 31;
    if (w >= e) return;
    int s = load_src(ei, e, w);
    int d = load_dst(ei, e, w);
    float nrm = g_dinv[s] * ew[w] * g_dinv[d];
    const float* xs = g_xw1 + (long)s * H1;
    float* ad = g_agg1 + (long)d * H1;
    atomicAdd(&ad[lane],      xs[lane]      * nrm);
    atomicAdd(&ad[lane + 32], xs[lane + 32] * nrm);
}

// Column sum / sum-of-squares for BN (bias cancels under mean subtraction).
template <int H>
__global__ void k_bnstats(const float* __restrict__ a, float* __restrict__ sum,
                          float* __restrict__ sq, int n) {
    __shared__ float ss[256], qq[256];
    int tid = threadIdx.x;
    int col = tid % H;
    int stripe = tid / H;
    const int NS = 256 / H;
    float s = 0.f, q = 0.f;
    for (int r = blockIdx.x * NS + stripe; r < n; r += gridDim.x * NS) {
        float v = a[(long)r * H + col];
        s += v;
        q += v * v;
    }
    ss[tid] = s; qq[tid] = q;
    __syncthreads();
    if (stripe == 0) {
#pragma unroll
        for (int k = 1; k < NS; k++) { s += ss[col + k * H]; q += qq[col + k * H]; }
        atomicAdd(&sum[col], s);
        atomicAdd(&sq[col],  q);
    }
}

template <int H>
__global__ void k_bnfin(const float* __restrict__ sum, const float* __restrict__ sq,
                        const float* __restrict__ g, const float* __restrict__ be,
                        float* __restrict__ scale, float* __restrict__ shift, int n) {
    int i = threadIdx.x;
    if (i < H) {
        float m = sum[i] / (float)n;
        float v = sq[i] / (float)n - m * m;
        float s = g[i] * rsqrtf(v + 1e-5f);
        scale[i] = s;
        shift[i] = be[i] - m * s;
    }
}

// h1n = relu(bn1(agg1)); xw2 = h1n @ W2; agg2 = xw2*invdeg.  Row-per-thread.
__global__ __launch_bounds__(256) void k_gemm2(const float* __restrict__ W2, int n) {
    __shared__ float ws[H1 * H2];  // 8 KB
    __shared__ float s1[H1], t1[H1];
    int tid = threadIdx.x;
    for (int i = tid; i < H1 * H2; i += blockDim.x) ws[i] = W2[i];
    if (tid < H1) { s1[tid] = g_scale1[tid]; t1[tid] = g_shift1[tid]; }
    __syncthreads();

    int row = blockIdx.x * blockDim.x + tid;
    if (row >= n) return;

    float acc[H2];
#pragma unroll
    for (int c = 0; c < H2; c++) acc[c] = 0.f;

    const float4* ar = (const float4*)(g_agg1 + (long)row * H1);
#pragma unroll 1
    for (int kb = 0; kb < H1 / 4; kb++) {
        float4 av = ar[kb];
        float vv[4] = {av.x, av.y, av.z, av.w};
#pragma unroll
        for (int u = 0; u < 4; u++) {
            int k = kb * 4 + u;
            float v = fmaxf(vv[u] * s1[k] + t1[k], 0.f);
            const float* w = ws + k * H2;
#pragma unroll
            for (int c = 0; c < H2; c++) acc[c] += v * w[c];
        }
    }
    float inv = g_invdeg[row];
    long base = (long)row * H2;
#pragma unroll
    for (int c = 0; c < H2; c++) {
        g_xw2[base + c]  = acc[c];
        g_agg2[base + c] = acc[c] * inv;
    }
}

// agg2[dst] += xw2[src]*norm; warp per edge, 32 features.
__global__ void k_scatter2(const void* ei, const float* __restrict__ ew, int e) {
    int gt   = blockIdx.x * blockDim.x + threadIdx.x;
    int w    = gt >> 5;
    int lane = gt & 31;
    if (w >= e) return;
    int s = load_src(ei, e, w);
    int d = load_dst(ei, e, w);
    float nrm = g_dinv[s] * ew[w] * g_dinv[d];
    atomicAdd(&g_agg2[(long)d * H2 + lane], g_xw2[(long)s * H2 + lane] * nrm);
}

// out[row] = relu(bn2(agg2[row])) . Wl + bl   (warp per row)
__global__ void k_final(const float* __restrict__ Wl, const float* __restrict__ bl,
                        float* __restrict__ out, int n) {
    int gt   = blockIdx.x * blockDim.x + threadIdx.x;
    int row  = gt >> 5;
    int lane = gt & 31;
    if (row >= n) return;
    float v = g_agg2[(long)row * H2 + lane];
    v = fmaxf(v * g_scale2[lane] + g_shift2[lane], 0.f) * Wl[lane];
#pragma unroll
    for (int off = 16; off > 0; off >>= 1)
        v += __shfl_xor_sync(0xFFFFFFFFu, v, off);
    if (lane == 0) out[row] = v + bl[0];
}

// ---------------- launch ----------------
extern "C" void kernel_launch(void* const* d_in, const int* in_sizes, int n_in,
                              void* d_out, int out_size) {
    const float* x  = (const float*)d_in[0];
    const void*  ei = d_in[1];
    const float* ew = (const float*)d_in[2];
    const float* W1 = (const float*)d_in[3];
    const float* g1 = (const float*)d_in[5];
    const float* be1= (const float*)d_in[6];
    const float* W2 = (const float*)d_in[7];
    const float* g2 = (const float*)d_in[9];
    const float* be2= (const float*)d_in[10];
    const float* Wl = (const float*)d_in[11];
    const float* bl = (const float*)d_in[12];
    float* out = (float*)d_out;

    int n = in_sizes[0] / FIN;   // 100000
    int e = in_sizes[2];         // 1600000

    float *p_sum1, *p_sq1, *p_sc1, *p_sh1, *p_sum2, *p_sq2, *p_sc2, *p_sh2, *p_agg1, *p_agg2;
    cudaGetSymbolAddress((void**)&p_sum1, g_sum1);
    cudaGetSymbolAddress((void**)&p_sq1,  g_sq1);
    cudaGetSymbolAddress((void**)&p_sc1,  g_scale1);
    cudaGetSymbolAddress((void**)&p_sh1,  g_shift1);
    cudaGetSymbolAddress((void**)&p_sum2, g_sum2);
    cudaGetSymbolAddress((void**)&p_sq2,  g_sq2);
    cudaGetSymbolAddress((void**)&p_sc2,  g_scale2);
    cudaGetSymbolAddress((void**)&p_sh2,  g_shift2);
    cudaGetSymbolAddress((void**)&p_agg1, g_agg1);
    cudaGetSymbolAddress((void**)&p_agg2, g_agg2);

    int tb = 256;
    int gN  = (n + tb - 1) / tb;
    int gE  = (e + tb - 1) / tb;
    int gEw = (e * 32 + tb - 1) / tb;     // warp per edge
    int gNw = (n * 32 + tb - 1) / tb;     // warp per row

    k_detect<<<1, 32>>>(ei, n, e);
    k_zero<<<gN, tb>>>(n);
    k_deg<<<gE, tb>>>(ei, ew, e);
    k_degfin<<<gN, tb>>>(n);

    k_gemm1<<<gN, tb>>>(x, W1, n);
    k_scatter1<<<gEw, tb>>>(ei, ew, e);

    k_bnstats<H1><<<512, tb>>>(p_agg1, p_sum1, p_sq1, n);
    k_bnfin<H1><<<1, H1>>>(p_sum1, p_sq1, g1, be1, p_sc1, p_sh1, n);

    k_gemm2<<<gN, tb>>>(W2, n);
    k_scatter2<<<gEw, tb>>>(ei, ew, e);

    k_bnstats<H2><<<512, tb>>>(p_agg2, p_sum2, p_sq2, n);
    k_bnfin<H2><<<1, H2>>>(p_sum2, p_sq2, g2, be2, p_sc2, p_sh2, n);

    k_final<<<gNw, tb>>>(Wl, bl, out, n);
}

// round 2
// speedup vs baseline: 1.0201x; 1.0201x over previous
#include <cuda_runtime.h>

#define FIN 128
#define H1  64
#define H2  32
#define MAXN 100000
#define MAXE 1600000

// ---------------- device scratch (no allocations allowed) ----------------
__device__ float g_deg[MAXN];
__device__ float g_dinv[MAXN];
__device__ float g_invdeg[MAXN];
__device__ float g_xw1[MAXN * H1];
__device__ float g_agg1[MAXN * H1];
__device__ float g_xw2[MAXN * H2];
__device__ float g_agg2[MAXN * H2];
__device__ float g_sum1[H1], g_sq1[H1], g_scale1[H1], g_shift1[H1];
__device__ float g_sum2[H2], g_sq2[H2], g_scale2[H2], g_shift2[H2];
__device__ int   g_idx64;

// ---------------- helpers ----------------
__device__ __forceinline__ int load_src(const void* ei, int e, int i) {
    return g_idx64 ? (int)((const long long*)ei)[i] : ((const int*)ei)[i];
}
__device__ __forceinline__ int load_dst(const void* ei, int e, int i) {
    return g_idx64 ? (int)((const long long*)ei)[e + i] : ((const int*)ei)[e + i];
}

// ---------------- kernels ----------------

// Detect whether edge_index is int64 or int32 (deterministic, data-driven).
__global__ void k_detect(const void* ei, int n, int e) {
    if (threadIdx.x == 0 && blockIdx.x == 0) {
        const long long* p = (const long long*)ei;
        int m = e < 512 ? e : 512;
        int ok = 1;
        for (int i = 0; i < m; i++) {
            unsigned long long v = (unsigned long long)p[i];
            if (v >= (unsigned long long)n) { ok = 0; break; }
        }
        g_idx64 = ok;
    }
}

__global__ void k_zero(int n) {
    int i = blockIdx.x * blockDim.x + threadIdx.x;
    if (i < n) g_deg[i] = 0.f;
    if (i < H1) { g_sum1[i] = 0.f; g_sq1[i] = 0.f; }
    if (i < H2) { g_sum2[i] = 0.f; g_sq2[i] = 0.f; }
}

__global__ void k_deg(const void* ei, const float* __restrict__ ew, int e) {
    int i = blockIdx.x * blockDim.x + threadIdx.x;
    if (i >= e) return;
    int d = load_dst(ei, e, i);
    atomicAdd(&g_deg[d], ew[i]);
}

__global__ void k_degfin(int n) {
    int i = blockIdx.x * blockDim.x + threadIdx.x;
    if (i >= n) return;
    float d = g_deg[i] + 1.0f;
    g_dinv[i]   = rsqrtf(d);
    g_invdeg[i] = 1.0f / d;
}

// xw1 = x @ W1 ; agg1 = xw1 * invdeg (self-loop term).  Row-per-thread.
__global__ __launch_bounds__(256) void k_gemm1(const float* __restrict__ x,
                                               const float* __restrict__ W1, int n) {
    __shared__ float ws[FIN * H1];  // 32 KB
    int tid = threadIdx.x;
    for (int i = tid; i < FIN * H1 / 4; i += blockDim.x)
        ((float4*)ws)[i] = ((const float4*)W1)[i];
    __syncthreads();

    int row = blockIdx.x * blockDim.x + tid;
    if (row >= n) return;

    float acc[H1];
#pragma unroll
    for (int c = 0; c < H1; c++) acc[c] = 0.f;

    const float4* xr = (const float4*)(x + (long)row * FIN);
#pragma unroll 1
    for (int kb = 0; kb < FIN / 4; kb++) {
        float4 xv = xr[kb];
        const float* w0 = ws + (kb * 4) * H1;
#pragma unroll
        for (int c = 0; c < H1; c++) {
            acc[c] += xv.x * w0[c] + xv.y * w0[H1 + c]
                    + xv.z * w0[2 * H1 + c] + xv.w * w0[3 * H1 + c];
        }
    }
    float inv = g_invdeg[row];
    long base = (long)row * H1;
#pragma unroll
    for (int c = 0; c < H1; c++) {
        g_xw1[base + c]  = acc[c];
        g_agg1[base + c] = acc[c] * inv;
    }
}

// agg1[dst] += xw1[src] * (dinv[src]*ew*dinv[dst]);  warp per edge, 64 features.
__global__ void k_scatter1(const void* ei, const float* __restrict__ ew, int e) {
    int gt   = blockIdx.x * blockDim.x + threadIdx.x;
    int w    = gt >> 5;
    int lane = gt & 31;
    if (w >= e) return;
    int s = load_src(ei, e, w);
    int d = load_dst(ei, e, w);
    float nrm = g_dinv[s] * ew[w] * g_dinv[d];
    const float* xs = g_xw1 + (long)s * H1;
    float* ad = g_agg1 + (long)d * H1;
    atomicAdd(&ad[lane],      xs[lane]      * nrm);
    atomicAdd(&ad[lane + 32], xs[lane + 32] * nrm);
}

// Column sum / sum-of-squares for BN (bias cancels under mean subtraction).
template <int H>
__global__ void k_bnstats(const float* __restrict__ a, float* __restrict__ sum,
                          float* __restrict__ sq, int n) {
    __shared__ float ss[256], qq[256];
    int tid = threadIdx.x;
    int col = tid % H;
    int stripe = tid / H;
    const int NS = 256 / H;
    float s = 0.f, q = 0.f;
    for (int r = blockIdx.x * NS + stripe; r < n; r += gridDim.x * NS) {
        float v = a[(long)r * H + col];
        s += v;
        q += v * v;
    }
    ss[tid] = s; qq[tid] = q;
    __syncthreads();
    if (stripe == 0) {
#pragma unroll
        for (int k = 1; k < NS; k++) { s += ss[col + k * H]; q += qq[col + k * H]; }
        atomicAdd(&sum[col], s);
        atomicAdd(&sq[col],  q);
    }
}

template <int H>
__global__ void k_bnfin(const float* __restrict__ sum, const float* __restrict__ sq,
                        const float* __restrict__ g, const float* __restrict__ be,
                        float* __restrict__ scale, float* __restrict__ shift, int n) {
    int i = threadIdx.x;
    if (i < H) {
        float m = sum[i] / (float)n;
        float v = sq[i] / (float)n - m * m;
        float s = g[i] * rsqrtf(v + 1e-5f);
        scale[i] = s;
        shift[i] = be[i] - m * s;
    }
}

// h1n = relu(bn1(agg1)); xw2 = h1n @ W2; agg2 = xw2*invdeg.  Row-per-thread.
__global__ __launch_bounds__(256) void k_gemm2(const float* __restrict__ W2, int n) {
    __shared__ float ws[H1 * H2];  // 8 KB
    __shared__ float s1[H1], t1[H1];
    int tid = threadIdx.x;
    for (int i = tid; i < H1 * H2; i += blockDim.x) ws[i] = W2[i];
    if (tid < H1) { s1[tid] = g_scale1[tid]; t1[tid] = g_shift1[tid]; }
    __syncthreads();

    int row = blockIdx.x * blockDim.x + tid;
    if (row >= n) return;

    float acc[H2];
#pragma unroll
    for (int c = 0; c < H2; c++) acc[c] = 0.f;

    const float4* ar = (const float4*)(g_agg1 + (long)row * H1);
#pragma unroll 1
    for (int kb = 0; kb < H1 / 4; kb++) {
        float4 av = ar[kb];
        float vv[4] = {av.x, av.y, av.z, av.w};
#pragma unroll
        for (int u = 0; u < 4; u++) {
            int k = kb * 4 + u;
            float v = fmaxf(vv[u] * s1[k] + t1[k], 0.f);
            const float* w = ws + k * H2;
#pragma unroll
            for (int c = 0; c < H2; c++) acc[c] += v * w[c];
        }
    }
    float inv = g_invdeg[row];
    long base = (long)row * H2;
#pragma unroll
    for (int c = 0; c < H2; c++) {
        g_xw2[base + c]  = acc[c];
        g_agg2[base + c] = acc[c] * inv;
    }
}

// agg2[dst] += xw2[src]*norm; warp per edge, 32 features.
__global__ void k_scatter2(const void* ei, const float* __restrict__ ew, int e) {
    int gt   = blockIdx.x * blockDim.x + threadIdx.x;
    int w    = gt >> 5;
    int lane = gt & 31;
    if (w >= e) return;
    int s = load_src(ei, e, w);
    int d = load_dst(ei, e, w);
    float nrm = g_dinv[s] * ew[w] * g_dinv[d];
    atomicAdd(&g_agg2[(long)d * H2 + lane], g_xw2[(long)s * H2 + lane] * nrm);
}

// out[row] = relu(bn2(agg2[row])) . Wl + bl   (warp per row)
__global__ void k_final(const float* __restrict__ Wl, const float* __restrict__ bl,
                        float* __restrict__ out, int n) {
    int gt   = blockIdx.x * blockDim.x + threadIdx.x;
    int row  = gt >> 5;
    int lane = gt & 31;
    if (row >= n) return;
    float v = g_agg2[(long)row * H2 + lane];
    v = fmaxf(v * g_scale2[lane] + g_shift2[lane], 0.f) * Wl[lane];
#pragma unroll
    for (int off = 16; off > 0; off >>= 1)
        v += __shfl_xor_sync(0xFFFFFFFFu, v, off);
    if (lane == 0) out[row] = v + bl[0];
}

// ---------------- launch ----------------
extern "C" void kernel_launch(void* const* d_in, const int* in_sizes, int n_in,
                              void* d_out, int out_size) {
    const float* x  = (const float*)d_in[0];
    const void*  ei = d_in[1];
    const float* ew = (const float*)d_in[2];
    const float* W1 = (const float*)d_in[3];
    const float* g1 = (const float*)d_in[5];
    const float* be1= (const float*)d_in[6];
    const float* W2 = (const float*)d_in[7];
    const float* g2 = (const float*)d_in[9];
    const float* be2= (const float*)d_in[10];
    const float* Wl = (const float*)d_in[11];
    const float* bl = (const float*)d_in[12];
    float* out = (float*)d_out;

    int n = in_sizes[0] / FIN;   // 100000
    int e = in_sizes[2];         // 1600000

    float *p_sum1, *p_sq1, *p_sc1, *p_sh1, *p_sum2, *p_sq2, *p_sc2, *p_sh2, *p_agg1, *p_agg2;
    cudaGetSymbolAddress((void**)&p_sum1, g_sum1);
    cudaGetSymbolAddress((void**)&p_sq1,  g_sq1);
    cudaGetSymbolAddress((void**)&p_sc1,  g_scale1);
    cudaGetSymbolAddress((void**)&p_sh1,  g_shift1);
    cudaGetSymbolAddress((void**)&p_sum2, g_sum2);
    cudaGetSymbolAddress((void**)&p_sq2,  g_sq2);
    cudaGetSymbolAddress((void**)&p_sc2,  g_scale2);
    cudaGetSymbolAddress((void**)&p_sh2,  g_shift2);
    cudaGetSymbolAddress((void**)&p_agg1, g_agg1);
    cudaGetSymbolAddress((void**)&p_agg2, g_agg2);

    int tb = 256;
    int gN  = (n + tb - 1) / tb;
    int gE  = (e + tb - 1) / tb;
    int gEw = (e * 32 + tb - 1) / tb;     // warp per edge
    int gNw = (n * 32 + tb - 1) / tb;     // warp per row

    k_detect<<<1, 32>>>(ei, n, e);
    k_zero<<<gN, tb>>>(n);
    k_deg<<<gE, tb>>>(ei, ew, e);
    k_degfin<<<gN, tb>>>(n);

    k_gemm1<<<gN, tb>>>(x, W1, n);
    k_scatter1<<<gEw, tb>>>(ei, ew, e);

    k_bnstats<H1><<<512, tb>>>(p_agg1, p_sum1, p_sq1, n);
    k_bnfin<H1><<<1, H1>>>(p_sum1, p_sq1, g1, be1, p_sc1, p_sh1, n);

    k_gemm2<<<gN, tb>>>(W2, n);
    k_scatter2<<<gEw, tb>>>(ei, ew, e);

    k_bnstats<H2><<<512, tb>>>(p_agg2, p_sum2, p_sq2, n);
    k_bnfin<H2><<<1, H2>>>(p_sum2, p_sq2, g2, be2, p_sc2, p_sh2, n);

    k_final<<<gNw, tb>>>(Wl, bl, out, n);
}